// round 12
// baseline (speedup 1.0000x reference)
#include <cuda_runtime.h>
#include <cuda_bf16.h>
#include <cstdint>

#define B_ 4
#define C_ 256
#define D_ 32
#define N_ 4096
#define LOG2E 1.4426950408889634f

// ---------------- global scratch (no allocs allowed) ----------------
__device__ __align__(16) __nv_bfloat16 g_q[B_ * N_ * D_];               // (b, n, d), pre-scaled by log2e
__device__ __align__(16) __nv_bfloat16 g_k[B_ * N_ * D_];               // (b, n, d)
__device__ __align__(16) __nv_bfloat16 g_v[(size_t)B_ * C_ * N_];       // (b, c, n)

extern __shared__ char smem_raw[];

static __device__ __forceinline__ unsigned smem_u32(const void* p) {
    return (unsigned)__cvta_generic_to_shared(p);
}
static __device__ __forceinline__ void mma16816(float* c, const unsigned* a, const unsigned* b) {
    asm volatile(
        "mma.sync.aligned.m16n8k16.row.col.f32.bf16.bf16.f32 "
        "{%0,%1,%2,%3}, {%4,%5,%6,%7}, {%8,%9}, {%0,%1,%2,%3};\n"
        : "+f"(c[0]), "+f"(c[1]), "+f"(c[2]), "+f"(c[3])
        : "r"(a[0]), "r"(a[1]), "r"(a[2]), "r"(a[3]), "r"(b[0]), "r"(b[1]));
}
static __device__ __forceinline__ void ldmx4(unsigned* r, unsigned addr) {
    asm volatile("ldmatrix.sync.aligned.m8n8.x4.shared.b16 {%0,%1,%2,%3}, [%4];"
        : "=r"(r[0]), "=r"(r[1]), "=r"(r[2]), "=r"(r[3]) : "r"(addr));
}
static __device__ __forceinline__ float ex2f(float x) {
    float r; asm("ex2.approx.f32 %0, %1;" : "=f"(r) : "f"(x)); return r;
}
static __device__ __forceinline__ unsigned packb(float a, float b) {
    __nv_bfloat162 t = __floats2bfloat162_rn(a, b);
    return *reinterpret_cast<unsigned*>(&t);
}
static __device__ __forceinline__ void cp16(unsigned dst, const void* src) {
    asm volatile("cp.async.cg.shared.global [%0], [%1], 16;\n" :: "r"(dst), "l"(src) : "memory");
}
static __device__ __forceinline__ void cp_commit() {
    asm volatile("cp.async.commit_group;\n" ::: "memory");
}
static __device__ __forceinline__ void cp_wait0() {
    asm volatile("cp.async.wait_group 0;\n" ::: "memory");
}

// =====================================================================
// Merged projection kernel (V in bf16; Q pre-scaled by log2e).
// CTAs [0,128): Q/K projection. CTAs [128,384): V projection.
// =====================================================================
#define QKA 264
#define QKB 36
#define PVA 40
#define PVB 36
#define PROJ_SMEM ((64 * QKA + 128 * QKB) * 2)   // 43008

__global__ __launch_bounds__(256) void proj_kernel(
    const float* __restrict__ x,
    const float* __restrict__ qw, const float* __restrict__ qb,
    const float* __restrict__ kw, const float* __restrict__ kb,
    const float* __restrict__ vw, const float* __restrict__ vb)
{
    int tid = threadIdx.x, lane = tid & 31, w = tid >> 5;

    if (blockIdx.x < 128) {
        __nv_bfloat16* sA = (__nv_bfloat16*)smem_raw;   // [64][QKA]
        __nv_bfloat16* sB = sA + 64 * QKA;              // [128][QKB]
        int b  = blockIdx.x >> 5;
        int n0 = (blockIdx.x & 31) * 128;

        for (int i = tid; i < 64 * 64; i += 256) {
            int r = i >> 6, kq = (i & 63) * 4;
            const float* src = (r < 32) ? (qw + r * 256 + kq) : (kw + (r - 32) * 256 + kq);
            float sc = (r < 32) ? LOG2E : 1.f;
            float4 v = *(const float4*)src;
            __nv_bfloat16* dst = sA + r * QKA + kq;
            dst[0] = __float2bfloat16(v.x * sc); dst[1] = __float2bfloat16(v.y * sc);
            dst[2] = __float2bfloat16(v.z * sc); dst[3] = __float2bfloat16(v.w * sc);
        }

        int mo = (w >> 1) * 16;
        int no = (w & 1) * 64;
        float acc[8][4];
#pragma unroll
        for (int nt = 0; nt < 8; nt++)
#pragma unroll
            for (int e = 0; e < 4; e++) acc[nt][e] = 0.f;

        for (int k0 = 0; k0 < 256; k0 += 32) {
            __syncthreads();
            {
                int nb = (tid & 31) * 4, kb_ = (tid >> 5) * 4;
                float vals[4][4];
#pragma unroll
                for (int kk = 0; kk < 4; kk++) {
                    float4 v = *(const float4*)(x + ((size_t)b * C_ + k0 + kb_ + kk) * N_ + n0 + nb);
                    vals[kk][0] = v.x; vals[kk][1] = v.y; vals[kk][2] = v.z; vals[kk][3] = v.w;
                }
#pragma unroll
                for (int nn = 0; nn < 4; nn++) {
                    __nv_bfloat162* d = (__nv_bfloat162*)(sB + (nb + nn) * QKB + kb_);
                    d[0] = __floats2bfloat162_rn(vals[0][nn], vals[1][nn]);
                    d[1] = __floats2bfloat162_rn(vals[2][nn], vals[3][nn]);
                }
            }
            __syncthreads();
#pragma unroll
            for (int k2 = 0; k2 < 2; k2++) {
                int kk = k0 + k2 * 16 + (lane & 3) * 2;
                const __nv_bfloat16* ap = sA + (mo + (lane >> 2)) * QKA + kk;
                unsigned aF[4];
                aF[0] = *(const unsigned*)ap;
                aF[1] = *(const unsigned*)(ap + 8 * QKA);
                aF[2] = *(const unsigned*)(ap + 8);
                aF[3] = *(const unsigned*)(ap + 8 * QKA + 8);
                int kl = k2 * 16 + (lane & 3) * 2;
#pragma unroll
                for (int nt = 0; nt < 8; nt++) {
                    const __nv_bfloat16* bp = sB + (no + nt * 8 + (lane >> 2)) * QKB + kl;
                    unsigned bF[2] = { *(const unsigned*)bp, *(const unsigned*)(bp + 8) };
                    mma16816(acc[nt], aF, bF);
                }
            }
        }

        int d = mo + (lane >> 2);
        bool isq = d < 32;
        int dd = isq ? d : d - 32;
        __nv_bfloat16* dst = isq ? g_q : g_k;
        const float* bias = isq ? qb : kb;
        float bsc = isq ? LOG2E : 1.f;
        float b0 = bias[dd] * bsc, b1 = bias[dd + 8] * bsc;
#pragma unroll
        for (int nt = 0; nt < 8; nt++) {
            int n = n0 + no + nt * 8 + (lane & 3) * 2;
            size_t base = ((size_t)b * N_ + n) * D_ + dd;
            dst[base]          = __float2bfloat16(acc[nt][0] + b0);
            dst[base + D_]     = __float2bfloat16(acc[nt][1] + b0);
            dst[base + 8]      = __float2bfloat16(acc[nt][2] + b1);
            dst[base + 8 + D_] = __float2bfloat16(acc[nt][3] + b1);
        }
    } else {
        __nv_bfloat16* sA = (__nv_bfloat16*)smem_raw;   // [128][PVA]
        __nv_bfloat16* sB = sA + 128 * PVA;             // [128][PVB]
        int i  = blockIdx.x - 128;
        int n0 = (i & 31) * 128;
        int c0 = ((i >> 5) & 1) * 128;
        int b  = i >> 6;
        int mo = (w >> 1) * 32;
        int no = (w & 1) * 64;

        float acc[2][8][4];
#pragma unroll
        for (int tm = 0; tm < 2; tm++)
#pragma unroll
            for (int nt = 0; nt < 8; nt++)
#pragma unroll
                for (int e = 0; e < 4; e++) acc[tm][nt][e] = 0.f;

        for (int k0 = 0; k0 < 256; k0 += 32) {
            __syncthreads();
            {
                int r = tid >> 1, cb = (tid & 1) * 16;
                const float4* src = (const float4*)(vw + (size_t)(c0 + r) * 256 + k0 + cb);
                __nv_bfloat16* dst = sA + r * PVA + cb;
#pragma unroll
                for (int j = 0; j < 4; j++) {
                    float4 v = src[j];
                    dst[j * 4 + 0] = __float2bfloat16(v.x);
                    dst[j * 4 + 1] = __float2bfloat16(v.y);
                    dst[j * 4 + 2] = __float2bfloat16(v.z);
                    dst[j * 4 + 3] = __float2bfloat16(v.w);
                }
            }
            {
                int nb = (tid & 31) * 4, kb_ = (tid >> 5) * 4;
                float vals[4][4];
#pragma unroll
                for (int kk = 0; kk < 4; kk++) {
                    float4 v = *(const float4*)(x + ((size_t)b * C_ + k0 + kb_ + kk) * N_ + n0 + nb);
                    vals[kk][0] = v.x; vals[kk][1] = v.y; vals[kk][2] = v.z; vals[kk][3] = v.w;
                }
#pragma unroll
                for (int nn = 0; nn < 4; nn++) {
                    __nv_bfloat162* d = (__nv_bfloat162*)(sB + (nb + nn) * PVB + kb_);
                    d[0] = __floats2bfloat162_rn(vals[0][nn], vals[1][nn]);
                    d[1] = __floats2bfloat162_rn(vals[2][nn], vals[3][nn]);
                }
            }
            __syncthreads();
#pragma unroll
            for (int k2 = 0; k2 < 2; k2++) {
                int kk = k2 * 16 + (lane & 3) * 2;
                unsigned aF[2][4];
#pragma unroll
                for (int tm = 0; tm < 2; tm++) {
                    const __nv_bfloat16* ap = sA + (mo + tm * 16 + (lane >> 2)) * PVA + kk;
                    aF[tm][0] = *(const unsigned*)ap;
                    aF[tm][1] = *(const unsigned*)(ap + 8 * PVA);
                    aF[tm][2] = *(const unsigned*)(ap + 8);
                    aF[tm][3] = *(const unsigned*)(ap + 8 * PVA + 8);
                }
#pragma unroll
                for (int nt = 0; nt < 8; nt++) {
                    const __nv_bfloat16* bp = sB + (no + nt * 8 + (lane >> 2)) * PVB + kk;
                    unsigned bF[2];
                    bF[0] = *(const unsigned*)bp;
                    bF[1] = *(const unsigned*)(bp + 8);
                    mma16816(acc[0][nt], aF[0], bF);
                    mma16816(acc[1][nt], aF[1], bF);
                }
            }
        }
#pragma unroll
        for (int tm = 0; tm < 2; tm++) {
            int cr0 = c0 + mo + tm * 16 + (lane >> 2);
            float b0 = vb[cr0], b1 = vb[cr0 + 8];
#pragma unroll
            for (int nt = 0; nt < 8; nt++) {
                int n = n0 + no + nt * 8 + (lane & 3) * 2;
                *(__nv_bfloat162*)(g_v + ((size_t)b * C_ + cr0) * N_ + n) =
                    __floats2bfloat162_rn(acc[tm][nt][0] + b0, acc[tm][nt][1] + b0);
                *(__nv_bfloat162*)(g_v + ((size_t)b * C_ + cr0 + 8) * N_ + n) =
                    __floats2bfloat162_rn(acc[tm][nt][2] + b1, acc[tm][nt][3] + b1);
            }
        }
    }
}

// =====================================================================
// Kernel 3: fused flash attention + residual (mma.sync, ex2 softmax).
// Per tile: S(jt) mmas -> PV(jt-1) mmas (indep of softmax) -> softmax(jt).
// SINGLE sacc + SINGLE pa set (no spills). K x3, V x4 buffers;
// cp.async issued after the barrier; wait_group 0 each iteration.
// =====================================================================
#define BM 128
#define BK 64
#define QPAD 40
#define KPAD 40
#define VPAD 88
#define SQ_OFF 0                                // 10240
#define SK_OFF 10240
#define SKBUF  (BK * KPAD * 2)                  // 5120 (x3)
#define SV_OFF (SK_OFF + 3 * SKBUF)             // 25600
#define SVBUF  (C_ * VPAD * 2)                  // 45056 (x4)
#define OSM_PW (C_ * 20 * 4)                    // 20480/warp epilogue staging (overlaps)
#define FLASH_SMEM (SV_OFF + 4 * SVBUF)         // 205824 (>= 8*OSM_PW = 163840)
#define NTILE (N_ / BK)                         // 64

__global__ __launch_bounds__(256, 1) void flash_kernel(
    const float* __restrict__ x, const float* __restrict__ gamma, float* __restrict__ out)
{
    __nv_bfloat16* sQ = (__nv_bfloat16*)(smem_raw + SQ_OFF);

    int tid = threadIdx.x, lane = tid & 31, w = tid >> 5;
    int b  = blockIdx.y;
    int q0 = blockIdx.x * BM;

    // per-thread cp.async bases
    unsigned skb_u32 = smem_u32(smem_raw + SK_OFF) + (tid >> 2) * (KPAD * 2) + (tid & 3) * 16;
    const __nv_bfloat16* skb_src = g_k + ((size_t)b * N_ + (tid >> 2)) * D_ + (tid & 3) * 8;
    unsigned svb_u32 = smem_u32(smem_raw + SV_OFF) + (tid >> 3) * (VPAD * 2) + (tid & 7) * 16;
    const __nv_bfloat16* svb_src = g_v + ((size_t)b * C_ + (tid >> 3)) * N_ + (tid & 7) * 8;

    {   // Q tile 128x32
        const uint4* src = (const uint4*)(g_q + ((size_t)b * N_ + q0) * D_);
#pragma unroll
        for (int i = 0; i < 2; i++) {
            int idx = tid + i * 256;
            int r = idx >> 2, ch = idx & 3;
            *(uint4*)(sQ + r * QPAD + ch * 8) = src[idx];
        }
    }

    // prologue: K0->kb0, K1->kb1, V0->vb0, V1->vb1, one group, full wait
    cp16(skb_u32, skb_src);
    cp16(skb_u32 + SKBUF, skb_src + (size_t)BK * D_);
#pragma unroll
    for (int i = 0; i < 8; i++) {
        cp16(svb_u32 + i * 32 * (VPAD * 2), svb_src + (size_t)(i * 32) * N_);
        cp16(svb_u32 + SVBUF + i * 32 * (VPAD * 2), svb_src + (size_t)(i * 32) * N_ + BK);
    }
    cp_commit();
    cp_wait0();
    __syncthreads();

    unsigned aq[2][4];
    {
        const __nv_bfloat16* qp = sQ + (w * 16 + (lane >> 2)) * QPAD + (lane & 3) * 2;
#pragma unroll
        for (int ks = 0; ks < 2; ks++) {
            aq[ks][0] = *(const unsigned*)(qp + ks * 16);
            aq[ks][1] = *(const unsigned*)(qp + ks * 16 + 8 * QPAD);
            aq[ks][2] = *(const unsigned*)(qp + ks * 16 + 8);
            aq[ks][3] = *(const unsigned*)(qp + ks * 16 + 8 * QPAD + 8);
        }
    }

    float oacc[32][4];
#pragma unroll
    for (int nt = 0; nt < 32; nt++)
#pragma unroll
        for (int e = 0; e < 4; e++) oacc[nt][e] = 0.f;
    float l0 = 0.f, l1 = 0.f;

    unsigned sv_lm = smem_u32(smem_raw + SV_OFF)
        + ((lane & 7) + ((lane & 16) ? 8 : 0)) * (VPAD * 2)
        + ((lane & 8) ? 16 : 0);

    float sacc[8][4];
    unsigned pa[4][4] = {};

#pragma unroll 1
    for (int jt = 0; jt < NTILE; jt++) {
        cp_wait0();                      // group committed last iter landed
        __syncthreads();                 // all readers of recycled bufs done
        // prefetch K(jt+2), V(jt+2) — issued after barrier (no WAR)
        if (jt + 2 < NTILE) {
            int j2 = (jt + 2) * BK;
            cp16(skb_u32 + ((jt + 2) % 3) * SKBUF, skb_src + (size_t)j2 * D_);
            unsigned vd = svb_u32 + ((jt + 2) & 3) * SVBUF;
#pragma unroll
            for (int i = 0; i < 8; i++)
                cp16(vd + i * 32 * (VPAD * 2), svb_src + (size_t)(i * 32) * N_ + j2);
        }
        cp_commit();

        // ---- S(jt): 16 HMMAs into the single sacc ----
        {
            const __nv_bfloat16* sK =
                (const __nv_bfloat16*)(smem_raw + SK_OFF + (jt % 3) * SKBUF);
#pragma unroll
            for (int nt = 0; nt < 8; nt++)
#pragma unroll
                for (int e = 0; e < 4; e++) sacc[nt][e] = 0.f;
#pragma unroll
            for (int ks = 0; ks < 2; ks++)
#pragma unroll
                for (int nt = 0; nt < 8; nt++) {
                    const __nv_bfloat16* kp = sK + (nt * 8 + (lane >> 2)) * KPAD
                        + ks * 16 + (lane & 3) * 2;
                    unsigned bF[2] = { *(const unsigned*)kp, *(const unsigned*)(kp + 8) };
                    mma16816(sacc[nt], aq[ks], bF);
                }
        }

        // ---- PV(jt-1): 128 HMMAs, independent of softmax(jt) ----
        if (jt > 0) {
            unsigned svb = sv_lm + ((jt - 1) & 3) * SVBUF;
#pragma unroll
            for (int ks = 0; ks < 4; ks++)
#pragma unroll
                for (int np = 0; np < 16; np++) {
                    unsigned bF[4];
                    ldmx4(bF, svb + np * 16 * (VPAD * 2) + ks * 32);
                    mma16816(oacc[np * 2 + 0], pa[ks], bF + 0);
                    mma16816(oacc[np * 2 + 1], pa[ks], bF + 2);
                }
        }

        // ---- softmax(jt): under the mma shadow; overwrites pa in place ----
#pragma unroll
        for (int nt = 0; nt < 8; nt++) {
            sacc[nt][0] = ex2f(sacc[nt][0]);
            sacc[nt][1] = ex2f(sacc[nt][1]);
            sacc[nt][2] = ex2f(sacc[nt][2]);
            sacc[nt][3] = ex2f(sacc[nt][3]);
            l0 += sacc[nt][0] + sacc[nt][1];
            l1 += sacc[nt][2] + sacc[nt][3];
        }
#pragma unroll
        for (int s = 0; s < 4; s++) {
            pa[s][0] = packb(sacc[2 * s][0],     sacc[2 * s][1]);
            pa[s][1] = packb(sacc[2 * s][2],     sacc[2 * s][3]);
            pa[s][2] = packb(sacc[2 * s + 1][0], sacc[2 * s + 1][1]);
            pa[s][3] = packb(sacc[2 * s + 1][2], sacc[2 * s + 1][3]);
        }
    }

    // final PV(NTILE-1): V buffer 3 stable since iter 61
    {
        unsigned svb = sv_lm + ((NTILE - 1) & 3) * SVBUF;
#pragma unroll
        for (int ks = 0; ks < 4; ks++)
#pragma unroll
            for (int np = 0; np < 16; np++) {
                unsigned bF[4];
                ldmx4(bF, svb + np * 16 * (VPAD * 2) + ks * 32);
                mma16816(oacc[np * 2 + 0], pa[ks], bF + 0);
                mma16816(oacc[np * 2 + 1], pa[ks], bF + 2);
            }
    }

    // reduce l partials across the quad
    l0 += __shfl_xor_sync(0xffffffffu, l0, 1);
    l0 += __shfl_xor_sync(0xffffffffu, l0, 2);
    l1 += __shfl_xor_sync(0xffffffffu, l1, 1);
    l1 += __shfl_xor_sync(0xffffffffu, l1, 2);

    __syncthreads();   // all warps done reading V smem before osm overwrites it

    // ---- epilogue: O/l * gamma, stage transposed (overlapping smem), store ----
    float g = gamma[0];
    float f0 = g / l0, f1 = g / l1;
    float* osm = (float*)(smem_raw + w * OSM_PW);  // [256][20] per warp
    int r0 = lane >> 2, r1 = r0 + 8;
#pragma unroll
    for (int nt = 0; nt < 32; nt++) {
        int c = nt * 8 + (lane & 3) * 2;
        osm[(c + 0) * 20 + r0] = oacc[nt][0] * f0;
        osm[(c + 1) * 20 + r0] = oacc[nt][1] * f0;
        osm[(c + 0) * 20 + r1] = oacc[nt][2] * f1;
        osm[(c + 1) * 20 + r1] = oacc[nt][3] * f1;
    }
    __syncwarp();
    int iw = q0 + w * 16;
    const float* xp = x + (size_t)b * C_ * N_ + iw;
    float* op = out + (size_t)b * C_ * N_ + iw;
    int cl = lane >> 2, i4 = (lane & 3) * 4;
    for (int cc = 0; cc < C_; cc += 8) {
        int c = cc + cl;
        float4 xv = *(const float4*)(xp + (size_t)c * N_ + i4);
        float4 sv = *(const float4*)(osm + c * 20 + i4);
        float4 ov;
        ov.x = xv.x + sv.x; ov.y = xv.y + sv.y;
        ov.z = xv.z + sv.z; ov.w = xv.w + sv.w;
        *(float4*)(op + (size_t)c * N_ + i4) = ov;
    }
}

// =====================================================================
extern "C" void kernel_launch(void* const* d_in, const int* in_sizes, int n_in,
                              void* d_out, int out_size)
{
    const float* x     = (const float*)d_in[0];
    const float* qw    = (const float*)d_in[1];
    const float* qb    = (const float*)d_in[2];
    const float* kw    = (const float*)d_in[3];
    const float* kb    = (const float*)d_in[4];
    const float* vw    = (const float*)d_in[5];
    const float* vb    = (const float*)d_in[6];
    const float* gamma = (const float*)d_in[7];
    float* out = (float*)d_out;

    cudaFuncSetAttribute(flash_kernel, cudaFuncAttributeMaxDynamicSharedMemorySize, FLASH_SMEM);

    proj_kernel<<<dim3(384), 256, PROJ_SMEM>>>(x, qw, qb, kw, kb, vw, vb);
    flash_kernel<<<dim3(N_ / BM, B_), 256, FLASH_SMEM>>>(x, gamma, out);
}

// round 13
// speedup vs baseline: 1.1257x; 1.1257x over previous
#include <cuda_runtime.h>
#include <cuda_bf16.h>
#include <cstdint>

#define B_ 4
#define C_ 256
#define D_ 32
#define N_ 4096
#define LOG2E 1.4426950408889634f

// ---------------- global scratch (no allocs allowed) ----------------
__device__ __align__(16) __nv_bfloat16 g_q[B_ * N_ * D_];               // (b, n, d), pre-scaled by log2e
__device__ __align__(16) __nv_bfloat16 g_k[B_ * N_ * D_];               // (b, n, d)
__device__ __align__(16) __nv_bfloat16 g_v[(size_t)B_ * C_ * N_];       // (b, c, n)

extern __shared__ char smem_raw[];

static __device__ __forceinline__ unsigned smem_u32(const void* p) {
    return (unsigned)__cvta_generic_to_shared(p);
}
static __device__ __forceinline__ void mma16816(float* c, const unsigned* a, const unsigned* b) {
    asm volatile(
        "mma.sync.aligned.m16n8k16.row.col.f32.bf16.bf16.f32 "
        "{%0,%1,%2,%3}, {%4,%5,%6,%7}, {%8,%9}, {%0,%1,%2,%3};\n"
        : "+f"(c[0]), "+f"(c[1]), "+f"(c[2]), "+f"(c[3])
        : "r"(a[0]), "r"(a[1]), "r"(a[2]), "r"(a[3]), "r"(b[0]), "r"(b[1]));
}
static __device__ __forceinline__ void ldmx4(unsigned* r, unsigned addr) {
    asm volatile("ldmatrix.sync.aligned.m8n8.x4.shared.b16 {%0,%1,%2,%3}, [%4];"
        : "=r"(r[0]), "=r"(r[1]), "=r"(r[2]), "=r"(r[3]) : "r"(addr));
}
static __device__ __forceinline__ float ex2f(float x) {
    float r; asm("ex2.approx.f32 %0, %1;" : "=f"(r) : "f"(x)); return r;
}
static __device__ __forceinline__ unsigned packb(float a, float b) {
    __nv_bfloat162 t = __floats2bfloat162_rn(a, b);
    return *reinterpret_cast<unsigned*>(&t);
}
static __device__ __forceinline__ void cp16(unsigned dst, const void* src) {
    asm volatile("cp.async.cg.shared.global [%0], [%1], 16;\n" :: "r"(dst), "l"(src) : "memory");
}
static __device__ __forceinline__ void cp_commit() {
    asm volatile("cp.async.commit_group;\n" ::: "memory");
}
static __device__ __forceinline__ void cp_wait1() {
    asm volatile("cp.async.wait_group 1;\n" ::: "memory");
}
static __device__ __forceinline__ void cp_wait0() {
    asm volatile("cp.async.wait_group 0;\n" ::: "memory");
}

// =====================================================================
// Merged projection kernel (V in bf16; Q pre-scaled by log2e).
// CTAs [0,128): Q/K projection. CTAs [128,384): V projection.
// =====================================================================
#define QKA 264
#define QKB 36
#define PVA 40
#define PVB 36
#define PROJ_SMEM ((64 * QKA + 128 * QKB) * 2)   // 43008

__global__ __launch_bounds__(256) void proj_kernel(
    const float* __restrict__ x,
    const float* __restrict__ qw, const float* __restrict__ qb,
    const float* __restrict__ kw, const float* __restrict__ kb,
    const float* __restrict__ vw, const float* __restrict__ vb)
{
    int tid = threadIdx.x, lane = tid & 31, w = tid >> 5;

    if (blockIdx.x < 128) {
        __nv_bfloat16* sA = (__nv_bfloat16*)smem_raw;   // [64][QKA]
        __nv_bfloat16* sB = sA + 64 * QKA;              // [128][QKB]
        int b  = blockIdx.x >> 5;
        int n0 = (blockIdx.x & 31) * 128;

        for (int i = tid; i < 64 * 64; i += 256) {
            int r = i >> 6, kq = (i & 63) * 4;
            const float* src = (r < 32) ? (qw + r * 256 + kq) : (kw + (r - 32) * 256 + kq);
            float sc = (r < 32) ? LOG2E : 1.f;
            float4 v = *(const float4*)src;
            __nv_bfloat16* dst = sA + r * QKA + kq;
            dst[0] = __float2bfloat16(v.x * sc); dst[1] = __float2bfloat16(v.y * sc);
            dst[2] = __float2bfloat16(v.z * sc); dst[3] = __float2bfloat16(v.w * sc);
        }

        int mo = (w >> 1) * 16;
        int no = (w & 1) * 64;
        float acc[8][4];
#pragma unroll
        for (int nt = 0; nt < 8; nt++)
#pragma unroll
            for (int e = 0; e < 4; e++) acc[nt][e] = 0.f;

        for (int k0 = 0; k0 < 256; k0 += 32) {
            __syncthreads();
            {
                int nb = (tid & 31) * 4, kb_ = (tid >> 5) * 4;
                float vals[4][4];
#pragma unroll
                for (int kk = 0; kk < 4; kk++) {
                    float4 v = *(const float4*)(x + ((size_t)b * C_ + k0 + kb_ + kk) * N_ + n0 + nb);
                    vals[kk][0] = v.x; vals[kk][1] = v.y; vals[kk][2] = v.z; vals[kk][3] = v.w;
                }
#pragma unroll
                for (int nn = 0; nn < 4; nn++) {
                    __nv_bfloat162* d = (__nv_bfloat162*)(sB + (nb + nn) * QKB + kb_);
                    d[0] = __floats2bfloat162_rn(vals[0][nn], vals[1][nn]);
                    d[1] = __floats2bfloat162_rn(vals[2][nn], vals[3][nn]);
                }
            }
            __syncthreads();
#pragma unroll
            for (int k2 = 0; k2 < 2; k2++) {
                int kk = k0 + k2 * 16 + (lane & 3) * 2;
                const __nv_bfloat16* ap = sA + (mo + (lane >> 2)) * QKA + kk;
                unsigned aF[4];
                aF[0] = *(const unsigned*)ap;
                aF[1] = *(const unsigned*)(ap + 8 * QKA);
                aF[2] = *(const unsigned*)(ap + 8);
                aF[3] = *(const unsigned*)(ap + 8 * QKA + 8);
                int kl = k2 * 16 + (lane & 3) * 2;
#pragma unroll
                for (int nt = 0; nt < 8; nt++) {
                    const __nv_bfloat16* bp = sB + (no + nt * 8 + (lane >> 2)) * QKB + kl;
                    unsigned bF[2] = { *(const unsigned*)bp, *(const unsigned*)(bp + 8) };
                    mma16816(acc[nt], aF, bF);
                }
            }
        }

        int d = mo + (lane >> 2);
        bool isq = d < 32;
        int dd = isq ? d : d - 32;
        __nv_bfloat16* dst = isq ? g_q : g_k;
        const float* bias = isq ? qb : kb;
        float bsc = isq ? LOG2E : 1.f;
        float b0 = bias[dd] * bsc, b1 = bias[dd + 8] * bsc;
#pragma unroll
        for (int nt = 0; nt < 8; nt++) {
            int n = n0 + no + nt * 8 + (lane & 3) * 2;
            size_t base = ((size_t)b * N_ + n) * D_ + dd;
            dst[base]          = __float2bfloat16(acc[nt][0] + b0);
            dst[base + D_]     = __float2bfloat16(acc[nt][1] + b0);
            dst[base + 8]      = __float2bfloat16(acc[nt][2] + b1);
            dst[base + 8 + D_] = __float2bfloat16(acc[nt][3] + b1);
        }
    } else {
        __nv_bfloat16* sA = (__nv_bfloat16*)smem_raw;   // [128][PVA]
        __nv_bfloat16* sB = sA + 128 * PVA;             // [128][PVB]
        int i  = blockIdx.x - 128;
        int n0 = (i & 31) * 128;
        int c0 = ((i >> 5) & 1) * 128;
        int b  = i >> 6;
        int mo = (w >> 1) * 32;
        int no = (w & 1) * 64;

        float acc[2][8][4];
#pragma unroll
        for (int tm = 0; tm < 2; tm++)
#pragma unroll
            for (int nt = 0; nt < 8; nt++)
#pragma unroll
                for (int e = 0; e < 4; e++) acc[tm][nt][e] = 0.f;

        for (int k0 = 0; k0 < 256; k0 += 32) {
            __syncthreads();
            {
                int r = tid >> 1, cb = (tid & 1) * 16;
                const float4* src = (const float4*)(vw + (size_t)(c0 + r) * 256 + k0 + cb);
                __nv_bfloat16* dst = sA + r * PVA + cb;
#pragma unroll
                for (int j = 0; j < 4; j++) {
                    float4 v = src[j];
                    dst[j * 4 + 0] = __float2bfloat16(v.x);
                    dst[j * 4 + 1] = __float2bfloat16(v.y);
                    dst[j * 4 + 2] = __float2bfloat16(v.z);
                    dst[j * 4 + 3] = __float2bfloat16(v.w);
                }
            }
            {
                int nb = (tid & 31) * 4, kb_ = (tid >> 5) * 4;
                float vals[4][4];
#pragma unroll
                for (int kk = 0; kk < 4; kk++) {
                    float4 v = *(const float4*)(x + ((size_t)b * C_ + k0 + kb_ + kk) * N_ + n0 + nb);
                    vals[kk][0] = v.x; vals[kk][1] = v.y; vals[kk][2] = v.z; vals[kk][3] = v.w;
                }
#pragma unroll
                for (int nn = 0; nn < 4; nn++) {
                    __nv_bfloat162* d = (__nv_bfloat162*)(sB + (nb + nn) * PVB + kb_);
                    d[0] = __floats2bfloat162_rn(vals[0][nn], vals[1][nn]);
                    d[1] = __floats2bfloat162_rn(vals[2][nn], vals[3][nn]);
                }
            }
            __syncthreads();
#pragma unroll
            for (int k2 = 0; k2 < 2; k2++) {
                int kk = k2 * 16 + (lane & 3) * 2;
                unsigned aF[2][4];
#pragma unroll
                for (int tm = 0; tm < 2; tm++) {
                    const __nv_bfloat16* ap = sA + (mo + tm * 16 + (lane >> 2)) * PVA + kk;
                    aF[tm][0] = *(const unsigned*)ap;
                    aF[tm][1] = *(const unsigned*)(ap + 8 * PVA);
                    aF[tm][2] = *(const unsigned*)(ap + 8);
                    aF[tm][3] = *(const unsigned*)(ap + 8 * PVA + 8);
                }
#pragma unroll
                for (int nt = 0; nt < 8; nt++) {
                    const __nv_bfloat16* bp = sB + (no + nt * 8 + (lane >> 2)) * PVB + kk;
                    unsigned bF[2];
                    bF[0] = *(const unsigned*)bp;
                    bF[1] = *(const unsigned*)(bp + 8);
                    mma16816(acc[0][nt], aF[0], bF);
                    mma16816(acc[1][nt], aF[1], bF);
                }
            }
        }
#pragma unroll
        for (int tm = 0; tm < 2; tm++) {
            int cr0 = c0 + mo + tm * 16 + (lane >> 2);
            float b0 = vb[cr0], b1 = vb[cr0 + 8];
#pragma unroll
            for (int nt = 0; nt < 8; nt++) {
                int n = n0 + no + nt * 8 + (lane & 3) * 2;
                *(__nv_bfloat162*)(g_v + ((size_t)b * C_ + cr0) * N_ + n) =
                    __floats2bfloat162_rn(acc[tm][nt][0] + b0, acc[tm][nt][1] + b0);
                *(__nv_bfloat162*)(g_v + ((size_t)b * C_ + cr0 + 8) * N_ + n) =
                    __floats2bfloat162_rn(acc[tm][nt][2] + b1, acc[tm][nt][3] + b1);
            }
        }
    }
}

// =====================================================================
// Kernel 3: fused flash attention + residual — R5 structure (the
// empirical best) + triple-buffered K/V (drops the tail barrier) +
// bare-ex2 softmax (log2e pre-folded into Q).
// =====================================================================
#define BM 128
#define BK 64
#define QPAD 40
#define KPAD 40
#define VPAD 88
#define SQ_OFF 0                                // 10240
#define SK_OFF 10240
#define SKBUF  (BK * KPAD * 2)                  // 5120 (x3)
#define SV_OFF (SK_OFF + 3 * SKBUF)             // 25600
#define SVBUF  (C_ * VPAD * 2)                  // 45056 (x3) -> ends 160768
#define OSM_PW (C_ * 20 * 4)                    // 20480 per warp (epilogue, overlaps)
#define FLASH_SMEM (8 * OSM_PW)                 // 163840 (covers mainloop's 160768)
#define NTILE (N_ / BK)                         // 64

__global__ __launch_bounds__(256, 1) void flash_kernel(
    const float* __restrict__ x, const float* __restrict__ gamma, float* __restrict__ out)
{
    __nv_bfloat16* sQ = (__nv_bfloat16*)(smem_raw + SQ_OFF);

    int tid = threadIdx.x, lane = tid & 31, w = tid >> 5;
    int b  = blockIdx.y;
    int q0 = blockIdx.x * BM;

    // per-thread cp.async bases
    unsigned skb_u32 = smem_u32(smem_raw + SK_OFF) + (tid >> 2) * (KPAD * 2) + (tid & 3) * 16;
    const __nv_bfloat16* skb_src = g_k + ((size_t)b * N_ + (tid >> 2)) * D_ + (tid & 3) * 8;
    unsigned svb_u32 = smem_u32(smem_raw + SV_OFF) + (tid >> 3) * (VPAD * 2) + (tid & 7) * 16;
    const __nv_bfloat16* svb_src = g_v + ((size_t)b * C_ + (tid >> 3)) * N_ + (tid & 7) * 8;

    {   // Q tile 128x32
        const uint4* src = (const uint4*)(g_q + ((size_t)b * N_ + q0) * D_);
#pragma unroll
        for (int i = 0; i < 2; i++) {
            int idx = tid + i * 256;
            int r = idx >> 2, ch = idx & 3;
            *(uint4*)(sQ + r * QPAD + ch * 8) = src[idx];
        }
    }

    // prologue: single group {K0->kb0, K1->kb1, V0->vb0}, full wait
    cp16(skb_u32, skb_src);
    cp16(skb_u32 + SKBUF, skb_src + (size_t)BK * D_);
#pragma unroll
    for (int i = 0; i < 8; i++)
        cp16(svb_u32 + i * 32 * (VPAD * 2), svb_src + (size_t)(i * 32) * N_);
    cp_commit();
    cp_wait0();
    __syncthreads();

    unsigned aq[2][4];
    {
        const __nv_bfloat16* qp = sQ + (w * 16 + (lane >> 2)) * QPAD + (lane & 3) * 2;
#pragma unroll
        for (int ks = 0; ks < 2; ks++) {
            aq[ks][0] = *(const unsigned*)(qp + ks * 16);
            aq[ks][1] = *(const unsigned*)(qp + ks * 16 + 8 * QPAD);
            aq[ks][2] = *(const unsigned*)(qp + ks * 16 + 8);
            aq[ks][3] = *(const unsigned*)(qp + ks * 16 + 8 * QPAD + 8);
        }
    }

    float oacc[32][4];
#pragma unroll
    for (int nt = 0; nt < 32; nt++)
#pragma unroll
        for (int e = 0; e < 4; e++) oacc[nt][e] = 0.f;
    float l0 = 0.f, l1 = 0.f;   // per-thread partials

    unsigned sv_lm = smem_u32(smem_raw + SV_OFF)
        + ((lane & 7) + ((lane & 16) ? 8 : 0)) * (VPAD * 2)
        + ((lane & 8) ? 16 : 0);

    float saccA[8][4], saccB[8][4];

    // S(0) from kb0 (no barrier needed after: kb0 refilled first at iter 1,
    // and the iter-0 barrier orders all warps past S(0) before that)
    {
        const __nv_bfloat16* sK = (const __nv_bfloat16*)(smem_raw + SK_OFF);
#pragma unroll
        for (int nt = 0; nt < 8; nt++)
#pragma unroll
            for (int e = 0; e < 4; e++) saccA[nt][e] = 0.f;
#pragma unroll
        for (int ks = 0; ks < 2; ks++)
#pragma unroll
            for (int nt = 0; nt < 8; nt++) {
                const __nv_bfloat16* kp = sK + (nt * 8 + (lane >> 2)) * KPAD + ks * 16 + (lane & 3) * 2;
                unsigned bF[2] = { *(const unsigned*)kp, *(const unsigned*)(kp + 8) };
                mma16816(saccA[nt], aq[ks], bF);
            }
    }

// macro local is jt_ (NOT jt) to avoid self-shadow.
// ONE barrier per tile: triple-buffered K/V make the tail barrier redundant
// (buffer refilled at iter jt was last read at iter jt-2; the iter-(jt-1)
// barrier orders all warps past that read before this iteration's cp).
#define FLASH_BODY(JT, CUR, NXT)                                                       \
    {                                                                                  \
        const int jt_ = (JT);                                                          \
        if (jt_ + 2 < NTILE)                                                           \
            cp16(skb_u32 + ((jt_ + 2) % 3) * SKBUF,                                    \
                 skb_src + (size_t)((jt_ + 2) * BK) * D_);                             \
        if (jt_ + 1 < NTILE) {                                                         \
            int j1 = (jt_ + 1) * BK;                                                   \
            unsigned vd = svb_u32 + ((jt_ + 1) % 3) * SVBUF;                           \
            _Pragma("unroll")                                                          \
            for (int i = 0; i < 8; i++)                                                \
                cp16(vd + i * 32 * (VPAD * 2), svb_src + (size_t)(i * 32) * N_ + j1);  \
        }                                                                              \
        cp_commit();                                                                   \
        cp_wait1(); /* K(jt_+1), V(jt_) ready */                                       \
        __syncthreads();                                                               \
        /* S(jt_+1) HMMA first: fills tensor queue while softmax ALU runs */           \
        if (jt_ + 1 < NTILE) {                                                         \
            const __nv_bfloat16* sK = (const __nv_bfloat16*)(smem_raw + SK_OFF         \
                + ((jt_ + 1) % 3) * SKBUF);                                            \
            _Pragma("unroll")                                                          \
            for (int nt = 0; nt < 8; nt++)                                             \
                _Pragma("unroll")                                                      \
                for (int e = 0; e < 4; e++) NXT[nt][e] = 0.f;                          \
            _Pragma("unroll")                                                          \
            for (int ks = 0; ks < 2; ks++)                                             \
                _Pragma("unroll")                                                      \
                for (int nt = 0; nt < 8; nt++) {                                       \
                    const __nv_bfloat16* kp = sK + (nt * 8 + (lane >> 2)) * KPAD       \
                        + ks * 16 + (lane & 3) * 2;                                    \
                    unsigned bF[2] = { *(const unsigned*)kp,                           \
                                       *(const unsigned*)(kp + 8) };                   \
                    mma16816(NXT[nt], aq[ks], bF);                                     \
                }                                                                      \
        }                                                                              \
        /* softmax: bare ex2 (log2e pre-folded into Q), per-thread l partials */       \
        _Pragma("unroll")                                                              \
        for (int nt = 0; nt < 8; nt++) {                                               \
            CUR[nt][0] = ex2f(CUR[nt][0]);                                             \
            CUR[nt][1] = ex2f(CUR[nt][1]);                                             \
            CUR[nt][2] = ex2f(CUR[nt][2]);                                             \
            CUR[nt][3] = ex2f(CUR[nt][3]);                                             \
            l0 += CUR[nt][0] + CUR[nt][1];                                             \
            l1 += CUR[nt][2] + CUR[nt][3];                                             \
        }                                                                              \
        unsigned pa[4][4];                                                             \
        _Pragma("unroll")                                                              \
        for (int s = 0; s < 4; s++) {                                                  \
            pa[s][0] = packb(CUR[2 * s][0],     CUR[2 * s][1]);                        \
            pa[s][1] = packb(CUR[2 * s][2],     CUR[2 * s][3]);                        \
            pa[s][2] = packb(CUR[2 * s + 1][0], CUR[2 * s + 1][1]);                    \
            pa[s][3] = packb(CUR[2 * s + 1][2], CUR[2 * s + 1][3]);                    \
        }                                                                              \
        /* O += P @ V^T (16 x 256 per warp) */                                         \
        unsigned svb = sv_lm + (jt_ % 3) * SVBUF;                                      \
        _Pragma("unroll")                                                              \
        for (int ks = 0; ks < 4; ks++)                                                 \
            _Pragma("unroll")                                                          \
            for (int np = 0; np < 16; np++) {                                          \
                unsigned bF[4];                                                        \
                ldmx4(bF, svb + np * 16 * (VPAD * 2) + ks * 32);                       \
                mma16816(oacc[np * 2 + 0], pa[ks], bF + 0);                            \
                mma16816(oacc[np * 2 + 1], pa[ks], bF + 2);                            \
            }                                                                          \
    }

#pragma unroll 1
    for (int jt = 0; jt < NTILE; jt += 2) {
        FLASH_BODY(jt,     saccA, saccB)
        FLASH_BODY(jt + 1, saccB, saccA)
    }

    // reduce l partials across the quad
    l0 += __shfl_xor_sync(0xffffffffu, l0, 1);
    l0 += __shfl_xor_sync(0xffffffffu, l0, 2);
    l1 += __shfl_xor_sync(0xffffffffu, l1, 1);
    l1 += __shfl_xor_sync(0xffffffffu, l1, 2);

    __syncthreads();   // all warps done with K/V smem before osm overwrites it

    // ---- epilogue: O/l * gamma, stage transposed (overlapping smem), store ----
    float g = gamma[0];
    float f0 = g / l0, f1 = g / l1;
    float* osm = (float*)(smem_raw + w * OSM_PW);  // [256][20] per warp
    int r0 = lane >> 2, r1 = r0 + 8;
#pragma unroll
    for (int nt = 0; nt < 32; nt++) {
        int c = nt * 8 + (lane & 3) * 2;
        osm[(c + 0) * 20 + r0] = oacc[nt][0] * f0;
        osm[(c + 1) * 20 + r0] = oacc[nt][1] * f0;
        osm[(c + 0) * 20 + r1] = oacc[nt][2] * f1;
        osm[(c + 1) * 20 + r1] = oacc[nt][3] * f1;
    }
    __syncwarp();
    int iw = q0 + w * 16;
    const float* xp = x + (size_t)b * C_ * N_ + iw;
    float* op = out + (size_t)b * C_ * N_ + iw;
    int cl = lane >> 2, i4 = (lane & 3) * 4;
    for (int cc = 0; cc < C_; cc += 8) {
        int c = cc + cl;
        float4 xv = *(const float4*)(xp + (size_t)c * N_ + i4);
        float4 sv = *(const float4*)(osm + c * 20 + i4);
        float4 ov;
        ov.x = xv.x + sv.x; ov.y = xv.y + sv.y;
        ov.z = xv.z + sv.z; ov.w = xv.w + sv.w;
        *(float4*)(op + (size_t)c * N_ + i4) = ov;
    }
}

// =====================================================================
extern "C" void kernel_launch(void* const* d_in, const int* in_sizes, int n_in,
                              void* d_out, int out_size)
{
    const float* x     = (const float*)d_in[0];
    const float* qw    = (const float*)d_in[1];
    const float* qb    = (const float*)d_in[2];
    const float* kw    = (const float*)d_in[3];
    const float* kb    = (const float*)d_in[4];
    const float* vw    = (const float*)d_in[5];
    const float* vb    = (const float*)d_in[6];
    const float* gamma = (const float*)d_in[7];
    float* out = (float*)d_out;

    cudaFuncSetAttribute(flash_kernel, cudaFuncAttributeMaxDynamicSharedMemorySize, FLASH_SMEM);

    proj_kernel<<<dim3(384), 256, PROJ_SMEM>>>(x, qw, qb, kw, kb, vw, vb);
    flash_kernel<<<dim3(N_ / BM, B_), 256, FLASH_SMEM>>>(x, gamma, out);
}

// round 15
// speedup vs baseline: 1.2245x; 1.0878x over previous
#include <cuda_runtime.h>
#include <cuda_bf16.h>
#include <cstdint>

#define B_ 4
#define C_ 256
#define D_ 32
#define N_ 4096
#define LOG2E 1.4426950408889634f

// ---------------- global scratch (no allocs allowed) ----------------
__device__ __align__(16) __nv_bfloat16 g_q[B_ * N_ * D_];               // (b, n, d), pre-scaled by log2e
__device__ __align__(16) __nv_bfloat16 g_k[B_ * N_ * D_];               // (b, n, d)
__device__ __align__(16) __nv_bfloat16 g_v[(size_t)B_ * C_ * N_];       // (b, c, n)

extern __shared__ char smem_raw[];

static __device__ __forceinline__ unsigned smem_u32(const void* p) {
    return (unsigned)__cvta_generic_to_shared(p);
}
static __device__ __forceinline__ void mma16816(float* c, const unsigned* a, const unsigned* b) {
    asm volatile(
        "mma.sync.aligned.m16n8k16.row.col.f32.bf16.bf16.f32 "
        "{%0,%1,%2,%3}, {%4,%5,%6,%7}, {%8,%9}, {%0,%1,%2,%3};\n"
        : "+f"(c[0]), "+f"(c[1]), "+f"(c[2]), "+f"(c[3])
        : "r"(a[0]), "r"(a[1]), "r"(a[2]), "r"(a[3]), "r"(b[0]), "r"(b[1]));
}
static __device__ __forceinline__ void ldmx4(unsigned* r, unsigned addr) {
    asm volatile("ldmatrix.sync.aligned.m8n8.x4.shared.b16 {%0,%1,%2,%3}, [%4];"
        : "=r"(r[0]), "=r"(r[1]), "=r"(r[2]), "=r"(r[3]) : "r"(addr));
}
static __device__ __forceinline__ float ex2f(float x) {
    float r; asm("ex2.approx.f32 %0, %1;" : "=f"(r) : "f"(x)); return r;
}
static __device__ __forceinline__ unsigned packb(float a, float b) {
    __nv_bfloat162 t = __floats2bfloat162_rn(a, b);
    return *reinterpret_cast<unsigned*>(&t);
}
static __device__ __forceinline__ void cp16(unsigned dst, const void* src) {
    asm volatile("cp.async.cg.shared.global [%0], [%1], 16;\n" :: "r"(dst), "l"(src) : "memory");
}
// mbarrier helpers
static __device__ __forceinline__ void mbar_init(unsigned mbar, unsigned cnt) {
    asm volatile("mbarrier.init.shared.b64 [%0], %1;" :: "r"(mbar), "r"(cnt) : "memory");
}
static __device__ __forceinline__ void mbar_arrive(unsigned mbar) {
    asm volatile("mbarrier.arrive.shared.b64 _, [%0];" :: "r"(mbar) : "memory");
}
// .noinc is LOAD-BEARING: without it the arrive first bumps the pending count
// and nets to zero, so a count-N barrier never completes (R14 hang).
static __device__ __forceinline__ void cp_arrive(unsigned mbar) {
    asm volatile("cp.async.mbarrier.arrive.noinc.shared.b64 [%0];" :: "r"(mbar) : "memory");
}
static __device__ __forceinline__ void mwait(unsigned mbar, unsigned phase) {
    asm volatile(
        "{\n\t.reg .pred P1;\n"
        "LAB_WAIT_%=:\n\t"
        "mbarrier.try_wait.parity.shared::cta.b64 P1, [%0], %1;\n\t"
        "@P1 bra.uni LAB_DONE_%=;\n\t"
        "bra.uni LAB_WAIT_%=;\n\t"
        "LAB_DONE_%=:\n\t}"
        :: "r"(mbar), "r"(phase) : "memory");
}

// =====================================================================
// Merged projection kernel (V in bf16; Q pre-scaled by log2e).
// CTAs [0,128): Q/K projection. CTAs [128,384): V projection.
// =====================================================================
#define QKA 264
#define QKB 36
#define PVA 40
#define PVB 36
#define PROJ_SMEM ((64 * QKA + 128 * QKB) * 2)   // 43008

__global__ __launch_bounds__(256) void proj_kernel(
    const float* __restrict__ x,
    const float* __restrict__ qw, const float* __restrict__ qb,
    const float* __restrict__ kw, const float* __restrict__ kb,
    const float* __restrict__ vw, const float* __restrict__ vb)
{
    int tid = threadIdx.x, lane = tid & 31, w = tid >> 5;

    if (blockIdx.x < 128) {
        __nv_bfloat16* sA = (__nv_bfloat16*)smem_raw;   // [64][QKA]
        __nv_bfloat16* sB = sA + 64 * QKA;              // [128][QKB]
        int b  = blockIdx.x >> 5;
        int n0 = (blockIdx.x & 31) * 128;

        for (int i = tid; i < 64 * 64; i += 256) {
            int r = i >> 6, kq = (i & 63) * 4;
            const float* src = (r < 32) ? (qw + r * 256 + kq) : (kw + (r - 32) * 256 + kq);
            float sc = (r < 32) ? LOG2E : 1.f;
            float4 v = *(const float4*)src;
            __nv_bfloat16* dst = sA + r * QKA + kq;
            dst[0] = __float2bfloat16(v.x * sc); dst[1] = __float2bfloat16(v.y * sc);
            dst[2] = __float2bfloat16(v.z * sc); dst[3] = __float2bfloat16(v.w * sc);
        }

        int mo = (w >> 1) * 16;
        int no = (w & 1) * 64;
        float acc[8][4];
#pragma unroll
        for (int nt = 0; nt < 8; nt++)
#pragma unroll
            for (int e = 0; e < 4; e++) acc[nt][e] = 0.f;

        for (int k0 = 0; k0 < 256; k0 += 32) {
            __syncthreads();
            {
                int nb = (tid & 31) * 4, kb_ = (tid >> 5) * 4;
                float vals[4][4];
#pragma unroll
                for (int kk = 0; kk < 4; kk++) {
                    float4 v = *(const float4*)(x + ((size_t)b * C_ + k0 + kb_ + kk) * N_ + n0 + nb);
                    vals[kk][0] = v.x; vals[kk][1] = v.y; vals[kk][2] = v.z; vals[kk][3] = v.w;
                }
#pragma unroll
                for (int nn = 0; nn < 4; nn++) {
                    __nv_bfloat162* d = (__nv_bfloat162*)(sB + (nb + nn) * QKB + kb_);
                    d[0] = __floats2bfloat162_rn(vals[0][nn], vals[1][nn]);
                    d[1] = __floats2bfloat162_rn(vals[2][nn], vals[3][nn]);
                }
            }
            __syncthreads();
#pragma unroll
            for (int k2 = 0; k2 < 2; k2++) {
                int kk = k0 + k2 * 16 + (lane & 3) * 2;
                const __nv_bfloat16* ap = sA + (mo + (lane >> 2)) * QKA + kk;
                unsigned aF[4];
                aF[0] = *(const unsigned*)ap;
                aF[1] = *(const unsigned*)(ap + 8 * QKA);
                aF[2] = *(const unsigned*)(ap + 8);
                aF[3] = *(const unsigned*)(ap + 8 * QKA + 8);
                int kl = k2 * 16 + (lane & 3) * 2;
#pragma unroll
                for (int nt = 0; nt < 8; nt++) {
                    const __nv_bfloat16* bp = sB + (no + nt * 8 + (lane >> 2)) * QKB + kl;
                    unsigned bF[2] = { *(const unsigned*)bp, *(const unsigned*)(bp + 8) };
                    mma16816(acc[nt], aF, bF);
                }
            }
        }

        int d = mo + (lane >> 2);
        bool isq = d < 32;
        int dd = isq ? d : d - 32;
        __nv_bfloat16* dst = isq ? g_q : g_k;
        const float* bias = isq ? qb : kb;
        float bsc = isq ? LOG2E : 1.f;
        float b0 = bias[dd] * bsc, b1 = bias[dd + 8] * bsc;
#pragma unroll
        for (int nt = 0; nt < 8; nt++) {
            int n = n0 + no + nt * 8 + (lane & 3) * 2;
            size_t base = ((size_t)b * N_ + n) * D_ + dd;
            dst[base]          = __float2bfloat16(acc[nt][0] + b0);
            dst[base + D_]     = __float2bfloat16(acc[nt][1] + b0);
            dst[base + 8]      = __float2bfloat16(acc[nt][2] + b1);
            dst[base + 8 + D_] = __float2bfloat16(acc[nt][3] + b1);
        }
    } else {
        __nv_bfloat16* sA = (__nv_bfloat16*)smem_raw;   // [128][PVA]
        __nv_bfloat16* sB = sA + 128 * PVA;             // [128][PVB]
        int i  = blockIdx.x - 128;
        int n0 = (i & 31) * 128;
        int c0 = ((i >> 5) & 1) * 128;
        int b  = i >> 6;
        int mo = (w >> 1) * 32;
        int no = (w & 1) * 64;

        float acc[2][8][4];
#pragma unroll
        for (int tm = 0; tm < 2; tm++)
#pragma unroll
            for (int nt = 0; nt < 8; nt++)
#pragma unroll
                for (int e = 0; e < 4; e++) acc[tm][nt][e] = 0.f;

        for (int k0 = 0; k0 < 256; k0 += 32) {
            __syncthreads();
            {
                int r = tid >> 1, cb = (tid & 1) * 16;
                const float4* src = (const float4*)(vw + (size_t)(c0 + r) * 256 + k0 + cb);
                __nv_bfloat16* dst = sA + r * PVA + cb;
#pragma unroll
                for (int j = 0; j < 4; j++) {
                    float4 v = src[j];
                    dst[j * 4 + 0] = __float2bfloat16(v.x);
                    dst[j * 4 + 1] = __float2bfloat16(v.y);
                    dst[j * 4 + 2] = __float2bfloat16(v.z);
                    dst[j * 4 + 3] = __float2bfloat16(v.w);
                }
            }
            {
                int nb = (tid & 31) * 4, kb_ = (tid >> 5) * 4;
                float vals[4][4];
#pragma unroll
                for (int kk = 0; kk < 4; kk++) {
                    float4 v = *(const float4*)(x + ((size_t)b * C_ + k0 + kb_ + kk) * N_ + n0 + nb);
                    vals[kk][0] = v.x; vals[kk][1] = v.y; vals[kk][2] = v.z; vals[kk][3] = v.w;
                }
#pragma unroll
                for (int nn = 0; nn < 4; nn++) {
                    __nv_bfloat162* d = (__nv_bfloat162*)(sB + (nb + nn) * PVB + kb_);
                    d[0] = __floats2bfloat162_rn(vals[0][nn], vals[1][nn]);
                    d[1] = __floats2bfloat162_rn(vals[2][nn], vals[3][nn]);
                }
            }
            __syncthreads();
#pragma unroll
            for (int k2 = 0; k2 < 2; k2++) {
                int kk = k2 * 16 + (lane & 3) * 2;
                unsigned aF[2][4];
#pragma unroll
                for (int tm = 0; tm < 2; tm++) {
                    const __nv_bfloat16* ap = sA + (mo + tm * 16 + (lane >> 2)) * PVA + kk;
                    aF[tm][0] = *(const unsigned*)ap;
                    aF[tm][1] = *(const unsigned*)(ap + 8 * PVA);
                    aF[tm][2] = *(const unsigned*)(ap + 8);
                    aF[tm][3] = *(const unsigned*)(ap + 8 * PVA + 8);
                }
#pragma unroll
                for (int nt = 0; nt < 8; nt++) {
                    const __nv_bfloat16* bp = sB + (no + nt * 8 + (lane >> 2)) * PVB + kk;
                    unsigned bF[2];
                    bF[0] = *(const unsigned*)bp;
                    bF[1] = *(const unsigned*)(bp + 8);
                    mma16816(acc[0][nt], aF[0], bF);
                    mma16816(acc[1][nt], aF[1], bF);
                }
            }
        }
#pragma unroll
        for (int tm = 0; tm < 2; tm++) {
            int cr0 = c0 + mo + tm * 16 + (lane >> 2);
            float b0 = vb[cr0], b1 = vb[cr0 + 8];
#pragma unroll
            for (int nt = 0; nt < 8; nt++) {
                int n = n0 + no + nt * 8 + (lane & 3) * 2;
                *(__nv_bfloat162*)(g_v + ((size_t)b * C_ + cr0) * N_ + n) =
                    __floats2bfloat162_rn(acc[tm][nt][0] + b0, acc[tm][nt][1] + b0);
                *(__nv_bfloat162*)(g_v + ((size_t)b * C_ + cr0 + 8) * N_ + n) =
                    __floats2bfloat162_rn(acc[tm][nt][2] + b1, acc[tm][nt][3] + b1);
            }
        }
    }
}

// =====================================================================
// Kernel 3: flash attention + residual — mbarrier-synced pipeline
// (no bar.sync in the mainloop; warps free-run with bounded drift).
// full[4] (count 256, cp.async .noinc arrivals): slot data ready.
// rd[4]   (count 8, lane0 arrivals): all warps done reading slot.
// =====================================================================
#define BM 128
#define BK 64
#define QPAD 40
#define KPAD 40
#define VPAD 88
#define SQ_OFF 0                                // 10240
#define SK_OFF 10240
#define SKBUF  (BK * KPAD * 2)                  // 5120 (x4)
#define SV_OFF (SK_OFF + 4 * SKBUF)             // 30720
#define SVBUF  (C_ * VPAD * 2)                  // 45056 (x4) -> ends 210944
#define MB_OFF 210944                           // full[4], rd[4]: 64 B
#define OSM_PW (C_ * 20 * 4)                    // 20480 per warp (epilogue, overlaps low smem)
#define FLASH_SMEM (MB_OFF + 64)                // 211008
#define NTILE (N_ / BK)                         // 64

__global__ __launch_bounds__(256, 1) void flash_kernel(
    const float* __restrict__ x, const float* __restrict__ gamma, float* __restrict__ out)
{
    __nv_bfloat16* sQ = (__nv_bfloat16*)(smem_raw + SQ_OFF);

    int tid = threadIdx.x, lane = tid & 31, w = tid >> 5;
    int b  = blockIdx.y;
    int q0 = blockIdx.x * BM;

    unsigned full_mb = smem_u32(smem_raw + MB_OFF);        // full[s] = +8s
    unsigned rd_mb   = smem_u32(smem_raw + MB_OFF) + 32;   // rd[s]   = +8s

    // per-thread cp.async bases
    unsigned skb_u32 = smem_u32(smem_raw + SK_OFF) + (tid >> 2) * (KPAD * 2) + (tid & 3) * 16;
    const __nv_bfloat16* skb_src = g_k + ((size_t)b * N_ + (tid >> 2)) * D_ + (tid & 3) * 8;
    unsigned svb_u32 = smem_u32(smem_raw + SV_OFF) + (tid >> 3) * (VPAD * 2) + (tid & 7) * 16;
    const __nv_bfloat16* svb_src = g_v + ((size_t)b * C_ + (tid >> 3)) * N_ + (tid & 7) * 8;

    {   // Q tile 128x32 (plain loads/stores)
        const uint4* src = (const uint4*)(g_q + ((size_t)b * N_ + q0) * D_);
#pragma unroll
        for (int i = 0; i < 2; i++) {
            int idx = tid + i * 256;
            int r = idx >> 2, ch = idx & 3;
            *(uint4*)(sQ + r * QPAD + ch * 8) = src[idx];
        }
    }

    if (tid == 0) {
#pragma unroll
        for (int s = 0; s < 4; s++) {
            mbar_init(full_mb + s * 8, 256);
            mbar_init(rd_mb + s * 8, 8);
        }
    }
    __syncthreads();   // Q visible + mbarriers initialized

    // pre-arm rd[0..3] completion #0 (8 warp-arrivals each)
    if (lane == 0) {
#pragma unroll
        for (int s = 0; s < 4; s++) mbar_arrive(rd_mb + s * 8);
    }

    // prologue fills: slot0 = {K0,V0}, slot1 = {K1,V1}
    cp16(skb_u32, skb_src);
#pragma unroll
    for (int i = 0; i < 8; i++)
        cp16(svb_u32 + i * 32 * (VPAD * 2), svb_src + (size_t)(i * 32) * N_);
    cp_arrive(full_mb);                  // full[0]
    cp16(skb_u32 + SKBUF, skb_src + (size_t)BK * D_);
#pragma unroll
    for (int i = 0; i < 8; i++)
        cp16(svb_u32 + SVBUF + i * 32 * (VPAD * 2), svb_src + (size_t)(i * 32) * N_ + BK);
    cp_arrive(full_mb + 8);              // full[1]

    unsigned aq[2][4];
    {
        const __nv_bfloat16* qp = sQ + (w * 16 + (lane >> 2)) * QPAD + (lane & 3) * 2;
#pragma unroll
        for (int ks = 0; ks < 2; ks++) {
            aq[ks][0] = *(const unsigned*)(qp + ks * 16);
            aq[ks][1] = *(const unsigned*)(qp + ks * 16 + 8 * QPAD);
            aq[ks][2] = *(const unsigned*)(qp + ks * 16 + 8);
            aq[ks][3] = *(const unsigned*)(qp + ks * 16 + 8 * QPAD + 8);
        }
    }

    float oacc[32][4];
#pragma unroll
    for (int nt = 0; nt < 32; nt++)
#pragma unroll
        for (int e = 0; e < 4; e++) oacc[nt][e] = 0.f;
    float l0 = 0.f, l1 = 0.f;

    unsigned sv_lm = smem_u32(smem_raw + SV_OFF)
        + ((lane & 7) + ((lane & 16) ? 8 : 0)) * (VPAD * 2)
        + ((lane & 8) ? 16 : 0);

    float saccA[8][4], saccB[8][4];

    // S(0): wait full[0] (parity 0), then compute
    if (lane == 0) mwait(full_mb, 0);
    __syncwarp();
    {
        const __nv_bfloat16* sK = (const __nv_bfloat16*)(smem_raw + SK_OFF);
#pragma unroll
        for (int nt = 0; nt < 8; nt++)
#pragma unroll
            for (int e = 0; e < 4; e++) saccA[nt][e] = 0.f;
#pragma unroll
        for (int ks = 0; ks < 2; ks++)
#pragma unroll
            for (int nt = 0; nt < 8; nt++) {
                const __nv_bfloat16* kp = sK + (nt * 8 + (lane >> 2)) * KPAD + ks * 16 + (lane & 3) * 2;
                unsigned bF[2] = { *(const unsigned*)kp, *(const unsigned*)(kp + 8) };
                mma16816(saccA[nt], aq[ks], bF);
            }
    }

// macro local is jt_ (NOT jt) to avoid self-shadow.
// Per iteration: [rd-wait + cp(jt+2) + cp-arrive] -> [full-wait + S(jt+1)]
// -> softmax(jt) -> PV(jt) -> rd-arrive(jt). No bar.sync in the loop.
#define FLASH_BODY(JT, CUR, NXT)                                                       \
    {                                                                                  \
        const int jt_ = (JT);                                                          \
        if (jt_ + 2 < NTILE) {                                                         \
            int s2 = (jt_ + 2) & 3;                                                    \
            if (lane == 0) mwait(rd_mb + s2 * 8, ((jt_ + 2) >> 2) & 1);                \
            __syncwarp();                                                              \
            int j2 = (jt_ + 2) * BK;                                                   \
            cp16(skb_u32 + s2 * SKBUF, skb_src + (size_t)j2 * D_);                     \
            unsigned vd = svb_u32 + s2 * SVBUF;                                        \
            _Pragma("unroll")                                                          \
            for (int i = 0; i < 8; i++)                                                \
                cp16(vd + i * 32 * (VPAD * 2), svb_src + (size_t)(i * 32) * N_ + j2);  \
            cp_arrive(full_mb + s2 * 8);                                               \
        }                                                                              \
        /* S(jt_+1): wait its slot's data, then fill tensor queue */                   \
        if (jt_ + 1 < NTILE) {                                                         \
            int s1 = (jt_ + 1) & 3;                                                    \
            if (lane == 0) mwait(full_mb + s1 * 8, ((jt_ + 1) >> 2) & 1);              \
            __syncwarp();                                                              \
            const __nv_bfloat16* sK =                                                  \
                (const __nv_bfloat16*)(smem_raw + SK_OFF + s1 * SKBUF);                \
            _Pragma("unroll")                                                          \
            for (int nt = 0; nt < 8; nt++)                                             \
                _Pragma("unroll")                                                      \
                for (int e = 0; e < 4; e++) NXT[nt][e] = 0.f;                          \
            _Pragma("unroll")                                                          \
            for (int ks = 0; ks < 2; ks++)                                             \
                _Pragma("unroll")                                                      \
                for (int nt = 0; nt < 8; nt++) {                                       \
                    const __nv_bfloat16* kp = sK + (nt * 8 + (lane >> 2)) * KPAD       \
                        + ks * 16 + (lane & 3) * 2;                                    \
                    unsigned bF[2] = { *(const unsigned*)kp,                           \
                                       *(const unsigned*)(kp + 8) };                   \
                    mma16816(NXT[nt], aq[ks], bF);                                     \
                }                                                                      \
        }                                                                              \
        /* softmax(jt_): bare ex2 (log2e pre-folded into Q) */                         \
        _Pragma("unroll")                                                              \
        for (int nt = 0; nt < 8; nt++) {                                               \
            CUR[nt][0] = ex2f(CUR[nt][0]);                                             \
            CUR[nt][1] = ex2f(CUR[nt][1]);                                             \
            CUR[nt][2] = ex2f(CUR[nt][2]);                                             \
            CUR[nt][3] = ex2f(CUR[nt][3]);                                             \
            l0 += CUR[nt][0] + CUR[nt][1];                                             \
            l1 += CUR[nt][2] + CUR[nt][3];                                             \
        }                                                                              \
        unsigned pa[4][4];                                                             \
        _Pragma("unroll")                                                              \
        for (int s = 0; s < 4; s++) {                                                  \
            pa[s][0] = packb(CUR[2 * s][0],     CUR[2 * s][1]);                        \
            pa[s][1] = packb(CUR[2 * s][2],     CUR[2 * s][3]);                        \
            pa[s][2] = packb(CUR[2 * s + 1][0], CUR[2 * s + 1][1]);                    \
            pa[s][3] = packb(CUR[2 * s + 1][2], CUR[2 * s + 1][3]);                    \
        }                                                                              \
        /* PV(jt_) from V slot jt_&3 */                                                \
        unsigned svb = sv_lm + (jt_ & 3) * SVBUF;                                      \
        _Pragma("unroll")                                                              \
        for (int ks = 0; ks < 4; ks++)                                                 \
            _Pragma("unroll")                                                          \
            for (int np = 0; np < 16; np++) {                                          \
                unsigned bF[4];                                                        \
                ldmx4(bF, svb + np * 16 * (VPAD * 2) + ks * 32);                       \
                mma16816(oacc[np * 2 + 0], pa[ks], bF + 0);                            \
                mma16816(oacc[np * 2 + 1], pa[ks], bF + 2);                            \
            }                                                                          \
        /* this warp is done reading slot jt_&3 (K part read last iter) */             \
        if (lane == 0) mbar_arrive(rd_mb + (jt_ & 3) * 8);                             \
    }

#pragma unroll 1
    for (int jt = 0; jt < NTILE; jt += 2) {
        FLASH_BODY(jt,     saccA, saccB)
        FLASH_BODY(jt + 1, saccB, saccA)
    }

    // reduce l partials across the quad
    l0 += __shfl_xor_sync(0xffffffffu, l0, 1);
    l0 += __shfl_xor_sync(0xffffffffu, l0, 2);
    l1 += __shfl_xor_sync(0xffffffffu, l1, 1);
    l1 += __shfl_xor_sync(0xffffffffu, l1, 2);

    __syncthreads();   // all warps done with K/V smem before osm overwrites it

    // ---- epilogue: O/l * gamma, stage transposed (overlapping smem), store ----
    float g = gamma[0];
    float f0 = g / l0, f1 = g / l1;
    float* osm = (float*)(smem_raw + w * OSM_PW);  // [256][20] per warp
    int r0 = lane >> 2, r1 = r0 + 8;
#pragma unroll
    for (int nt = 0; nt < 32; nt++) {
        int c = nt * 8 + (lane & 3) * 2;
        osm[(c + 0) * 20 + r0] = oacc[nt][0] * f0;
        osm[(c + 1) * 20 + r0] = oacc[nt][1] * f0;
        osm[(c + 0) * 20 + r1] = oacc[nt][2] * f1;
        osm[(c + 1) * 20 + r1] = oacc[nt][3] * f1;
    }
    __syncwarp();
    int iw = q0 + w * 16;
    const float* xp = x + (size_t)b * C_ * N_ + iw;
    float* op = out + (size_t)b * C_ * N_ + iw;
    int cl = lane >> 2, i4 = (lane & 3) * 4;
    for (int cc = 0; cc < C_; cc += 8) {
        int c = cc + cl;
        float4 xv = *(const float4*)(xp + (size_t)c * N_ + i4);
        float4 sv = *(const float4*)(osm + c * 20 + i4);
        float4 ov;
        ov.x = xv.x + sv.x; ov.y = xv.y + sv.y;
        ov.z = xv.z + sv.z; ov.w = xv.w + sv.w;
        *(float4*)(op + (size_t)c * N_ + i4) = ov;
    }
}

// =====================================================================
extern "C" void kernel_launch(void* const* d_in, const int* in_sizes, int n_in,
                              void* d_out, int out_size)
{
    const float* x     = (const float*)d_in[0];
    const float* qw    = (const float*)d_in[1];
    const float* qb    = (const float*)d_in[2];
    const float* kw    = (const float*)d_in[3];
    const float* kb    = (const float*)d_in[4];
    const float* vw    = (const float*)d_in[5];
    const float* vb    = (const float*)d_in[6];
    const float* gamma = (const float*)d_in[7];
    float* out = (float*)d_out;

    cudaFuncSetAttribute(flash_kernel, cudaFuncAttributeMaxDynamicSharedMemorySize, FLASH_SMEM);

    proj_kernel<<<dim3(384), 256, PROJ_SMEM>>>(x, qw, qb, kw, kb, vw, vb);
    flash_kernel<<<dim3(N_ / BM, B_), 256, FLASH_SMEM>>>(x, gamma, out);
}